// round 8
// baseline (speedup 1.0000x reference)
#include <cuda_runtime.h>
#include <cstdint>

#define NB 2
#define NNODES 5000
#define NEDGES 160000
#define FIN 128
#define HID 128
#define ED 16
#define INE 288          // 2*FIN + 16 + ED
#define MT 64            // edges per block
#define PAD_X 164        // phase-buffer stride (164 % 32 == 4 -> conflict-free A frags)
#define PAD_H 132        // hidden stride (132 % 32 == 4)
#define PSTR 40          // panel row stride (tig*8+g -> conflict-free B frags)
#define PANEL (8 * PSTR) // 320 floats per panel
#define NPB 8

// ---------------- scratch (allocation-free) ----------------
__device__ float g_agg_h[NB * NNODES * HID];
__device__ float g_agg_c[NB * NNODES * 12];
__device__ float g_cnt[NNODES];
__device__ __align__(16) float g_We1[INE * HID];
__device__ __align__(16) float g_We2[HID * HID];
__device__ __align__(16) float g_Wc1[HID * HID];

__device__ __forceinline__ float tf32r(float x) {
    uint32_t u;
    asm("cvt.rna.tf32.f32 %0, %1;" : "=r"(u) : "f"(x));
    return __uint_as_float(u);
}

__device__ __forceinline__ void mma_tf32(float c[4], uint32_t a0, uint32_t a1,
                                         uint32_t a2, uint32_t a3,
                                         uint32_t b0, uint32_t b1) {
    asm volatile(
        "mma.sync.aligned.m16n8k8.row.col.f32.tf32.tf32.f32 "
        "{%0,%1,%2,%3},{%4,%5,%6,%7},{%8,%9},{%0,%1,%2,%3};"
        : "+f"(c[0]), "+f"(c[1]), "+f"(c[2]), "+f"(c[3])
        : "r"(a0), "r"(a1), "r"(a2), "r"(a3), "r"(b0), "r"(b1));
}

__device__ __forceinline__ uint32_t smem_u32(const void* p) {
    return (uint32_t)__cvta_generic_to_shared(p);
}
#define CPA16(d, s) asm volatile("cp.async.ca.shared.global [%0], [%1], 16;" :: "r"(d), "l"(s) : "memory")
#define CPC()       asm volatile("cp.async.commit_group;" ::: "memory")
#define CPW(n)      asm volatile("cp.async.wait_group %0;" :: "n"(n) : "memory")

// ---------------- helper kernels ----------------
__global__ void zero_kernel() {
    const int T1 = NB * NNODES * HID;
    const int T2 = T1 + NB * NNODES * 12;
    const int total = T2 + NNODES;
    for (int i = blockIdx.x * blockDim.x + threadIdx.x; i < total;
         i += gridDim.x * blockDim.x) {
        if (i < T1)       g_agg_h[i] = 0.0f;
        else if (i < T2)  g_agg_c[i - T1] = 0.0f;
        else              g_cnt[i - T2] = 0.0f;
    }
}

__global__ void count_kernel(const int* __restrict__ edge_index) {
    int e = blockIdx.x * blockDim.x + threadIdx.x;
    if (e < NEDGES) atomicAdd(&g_cnt[edge_index[e]], 1.0f);
}

__global__ void prep_kernel(const float* __restrict__ W_e1,
                            const float* __restrict__ W_e2,
                            const float* __restrict__ W_c1) {
    int i = blockIdx.x * blockDim.x + threadIdx.x;
    if (i < INE * HID) g_We1[i] = tf32r(W_e1[i]);
    if (i < HID * HID) {
        g_We2[i] = tf32r(W_e2[i]);
        g_Wc1[i] = tf32r(W_c1[i]);
    }
}

// ---------------- mma GEMM with per-warp cp.async B panels ----------------
__device__ __forceinline__ void init_c(const float* __restrict__ bias,
                                       int n_base, int tig, float c[2][4][4]) {
    #pragma unroll
    for (int nj = 0; nj < 4; nj++) {
        float bv0 = bias[n_base + nj * 8 + 2 * tig];
        float bv1 = bias[n_base + nj * 8 + 2 * tig + 1];
        #pragma unroll
        for (int mi = 0; mi < 2; mi++) {
            c[mi][nj][0] = bv0; c[mi][nj][1] = bv1;
            c[mi][nj][2] = bv0; c[mi][nj][3] = bv1;
        }
    }
}

// KSTEPS k-steps of 8. A from smem (inS, stride PADIN), B streamed from Wg
// (row-major KxHID) via double-buffered per-warp panels (pb: 2*PANEL floats).
// Accumulates into c.
template<int KSTEPS, int PADIN>
__device__ __forceinline__ void mma_gemm_cp(
    const float* __restrict__ inS, const float* __restrict__ Wg,
    float* __restrict__ pb, int m_base, int n_base, int g, int tig, int lane,
    float c[2][4][4])
{
    const int pr = lane >> 2;          // panel row 0..7
    const int pc = (lane & 3) * 8;     // panel col 0,8,16,24
    const float* src0 = Wg + pr * HID + n_base + pc;
    {
        uint32_t d = smem_u32(pb + pr * PSTR + pc);
        CPA16(d, src0); CPA16(d + 16, src0 + 4); CPC();
    }
    #pragma unroll 2
    for (int s = 0; s < KSTEPS; s++) {
        if (s + 1 < KSTEPS) {
            const float* src = src0 + (s + 1) * 8 * HID;
            uint32_t d = smem_u32(pb + ((s + 1) & 1) * PANEL + pr * PSTR + pc);
            CPA16(d, src); CPA16(d + 16, src + 4); CPC();
            CPW(1);
        } else {
            CPW(0);
        }
        __syncwarp();
        const float* pan = pb + (s & 1) * PANEL;
        uint32_t a[2][4];
        #pragma unroll
        for (int mi = 0; mi < 2; mi++) {
            const float* xr = inS + (m_base + mi * 16 + g) * PADIN + s * 8 + tig;
            a[mi][0] = __float_as_uint(xr[0]);
            a[mi][1] = __float_as_uint(xr[8 * PADIN]);
            a[mi][2] = __float_as_uint(xr[4]);
            a[mi][3] = __float_as_uint(xr[8 * PADIN + 4]);
        }
        uint32_t b0[4], b1[4];
        #pragma unroll
        for (int nj = 0; nj < 4; nj++) {
            b0[nj] = __float_as_uint(pan[tig * PSTR + nj * 8 + g]);
            b1[nj] = __float_as_uint(pan[(tig + 4) * PSTR + nj * 8 + g]);
        }
        #pragma unroll
        for (int nj = 0; nj < 4; nj++)
            #pragma unroll
            for (int mi = 0; mi < 2; mi++)
                mma_tf32(c[mi][nj], a[mi][0], a[mi][1], a[mi][2], a[mi][3],
                         b0[nj], b1[nj]);
    }
}

// smem float offsets
#define OFF_XB  0                          // [MT][PAD_X] phase buffer (later efS)
#define OFF_H1  (MT * PAD_X)               // [MT][PAD_H] h1 (later h2)
#define OFF_PAN (OFF_H1 + MT * PAD_H)      // 8 warps * 2 * PANEL
#define OFF_CDS (OFF_PAN + 8 * 2 * PANEL)
#define OFF_WS  (OFF_CDS + MT * 12)
#define OFF_IDX (OFF_WS + MT * 4)
#define SMEM_FLOATS (OFF_IDX + 2 * MT)
#define SMEM_BYTES  (SMEM_FLOATS * 4)

__global__ __launch_bounds__(256, 2) void edge_kernel(
    const float* __restrict__ h, const float* __restrict__ coord,
    const int* __restrict__ edge_index, const float* __restrict__ edge_attr,
    const float* __restrict__ b_e1, const float* __restrict__ b_e2,
    const float* __restrict__ b_c1, const float* __restrict__ W_c2)
{
    extern __shared__ float sm[];
    float* xb   = sm + OFF_XB;    // phase buffer [MT][PAD_X]
    float* efS  = sm + OFF_XB;    // ef alias [MT][PAD_H] (xb dead after GEMM1)
    float* h1S  = sm + OFF_H1;    // h1 [MT][PAD_H]
    float* h2S  = sm + OFF_H1;    // h2 alias (h1 dead after GEMM2)
    float* cds  = sm + OFF_CDS;
    float* wsS  = sm + OFF_WS;
    int* rows_s = (int*)(sm + OFF_IDX);
    int* cols_s = rows_s + MT;

    const int t    = threadIdx.x;
    const int lane = t & 31;
    const int w    = t >> 5;
    const int g    = lane >> 2;
    const int tig  = lane & 3;
    const int m_base = (w >> 2) * 32;   // 2 m-warps
    const int n_base = (w & 3) * 32;    // 4 n-warps
    float* pb = sm + OFF_PAN + w * (2 * PANEL);

    const int e0 = blockIdx.x * MT;
    const int b  = blockIdx.y;
    const float* hb = h + (size_t)b * NNODES * FIN;
    const float* cb = coord + (size_t)b * NNODES * 12;

    if (t < MT) {
        rows_s[t] = edge_index[e0 + t];
        cols_s[t] = edge_index[NEDGES + e0 + t];
    }
    __syncthreads();

    // ---- phase A fill: h[row] into cols [0,128); cds ----
    for (int i = t; i < MT * FIN; i += 256) {
        int e = i >> 7, k = i & 127;
        xb[e * PAD_X + k] = tf32r(hb[rows_s[e] * FIN + k]);
    }
    for (int i = t; i < MT * 12; i += 256) {
        int e = i / 12, c = i % 12;
        cds[e * 12 + c] = cb[rows_s[e] * 12 + c] - cb[cols_s[e] * 12 + c];
    }
    __syncthreads();

    float c[2][4][4];
    init_c(b_e1, n_base, tig, c);
    // GEMM1 phase A: k = 0..127 (We1 rows 0..127)
    mma_gemm_cp<16, PAD_X>(xb, g_We1, pb, m_base, n_base, g, tig, lane, c);
    __syncthreads();   // all warps done reading xb

    // ---- phase B fill: h[col] cols [0,128), radial [128,144), attr [144,160) ----
    for (int i = t; i < MT * FIN; i += 256) {
        int e = i >> 7, k = i & 127;
        xb[e * PAD_X + k] = tf32r(hb[cols_s[e] * FIN + k]);
    }
    for (int i = t; i < MT * ED; i += 256) {
        int e = i >> 4, cc = i & 15;
        xb[e * PAD_X + 144 + cc] = tf32r(edge_attr[(size_t)(e0 + e) * ED + cc]);
    }
    if (t < MT) {
        float cd[12];
        #pragma unroll
        for (int cc = 0; cc < 12; cc++) cd[cc] = cds[t * 12 + cc];
        float prod[16], ss = 0.0f;
        #pragma unroll
        for (int j = 0; j < 4; j++)
            #pragma unroll
            for (int k = 0; k < 4; k++) {
                float p = cd[j*3]*cd[k*3] + cd[j*3+1]*cd[k*3+1] + cd[j*3+2]*cd[k*3+2];
                prod[j * 4 + k] = p;
                ss += p * p;
            }
        float inv = 1.0f / fmaxf(sqrtf(ss), 1e-12f);
        #pragma unroll
        for (int i = 0; i < 16; i++)
            xb[t * PAD_X + 128 + i] = tf32r(prod[i] * inv);
    }
    __syncthreads();

    // GEMM1 phase B: k = 0..159 local (We1 rows 128..287), accumulate
    mma_gemm_cp<20, PAD_X>(xb, g_We1 + 128 * HID, pb, m_base, n_base, g, tig, lane, c);

    // h1 = tf32(relu(c))
    #pragma unroll
    for (int nj = 0; nj < 4; nj++) {
        int col = n_base + nj * 8 + 2 * tig;
        #pragma unroll
        for (int mi = 0; mi < 2; mi++) {
            int r = m_base + mi * 16 + g;
            h1S[r * PAD_H + col]           = tf32r(fmaxf(c[mi][nj][0], 0.0f));
            h1S[r * PAD_H + col + 1]       = tf32r(fmaxf(c[mi][nj][1], 0.0f));
            h1S[(r + 8) * PAD_H + col]     = tf32r(fmaxf(c[mi][nj][2], 0.0f));
            h1S[(r + 8) * PAD_H + col + 1] = tf32r(fmaxf(c[mi][nj][3], 0.0f));
        }
    }
    __syncthreads();

    // GEMM2: h1 @ We2 -> relu -> ef (into xb region) ; scatter agg_h (fp32)
    init_c(b_e2, n_base, tig, c);
    mma_gemm_cp<16, PAD_H>(h1S, g_We2, pb, m_base, n_base, g, tig, lane, c);
    {
        float* aggh = g_agg_h + (size_t)b * NNODES * HID;
        #pragma unroll
        for (int nj = 0; nj < 4; nj++) {
            int col = n_base + nj * 8 + 2 * tig;
            #pragma unroll
            for (int mi = 0; mi < 2; mi++) {
                int r = m_base + mi * 16 + g;
                float v0 = fmaxf(c[mi][nj][0], 0.0f), v1 = fmaxf(c[mi][nj][1], 0.0f);
                float v2 = fmaxf(c[mi][nj][2], 0.0f), v3 = fmaxf(c[mi][nj][3], 0.0f);
                efS[r * PAD_H + col]           = tf32r(v0);
                efS[r * PAD_H + col + 1]       = tf32r(v1);
                efS[(r + 8) * PAD_H + col]     = tf32r(v2);
                efS[(r + 8) * PAD_H + col + 1] = tf32r(v3);
                atomicAdd(&aggh[rows_s[r] * HID + col],         v0);
                atomicAdd(&aggh[rows_s[r] * HID + col + 1],     v1);
                atomicAdd(&aggh[rows_s[r + 8] * HID + col],     v2);
                atomicAdd(&aggh[rows_s[r + 8] * HID + col + 1], v3);
            }
        }
    }
    __syncthreads();

    // GEMM3: ef @ Wc1 -> relu -> h2 (into h1 region)
    init_c(b_c1, n_base, tig, c);
    mma_gemm_cp<16, PAD_H>(efS, g_Wc1, pb, m_base, n_base, g, tig, lane, c);
    __syncthreads();   // all warps done reading efS/h1 before h2 overwrite
    #pragma unroll
    for (int nj = 0; nj < 4; nj++) {
        int col = n_base + nj * 8 + 2 * tig;
        #pragma unroll
        for (int mi = 0; mi < 2; mi++) {
            int r = m_base + mi * 16 + g;
            h2S[r * PAD_H + col]           = fmaxf(c[mi][nj][0], 0.0f);
            h2S[r * PAD_H + col + 1]       = fmaxf(c[mi][nj][1], 0.0f);
            h2S[(r + 8) * PAD_H + col]     = fmaxf(c[mi][nj][2], 0.0f);
            h2S[(r + 8) * PAD_H + col + 1] = fmaxf(c[mi][nj][3], 0.0f);
        }
    }
    __syncthreads();

    // GEMM4 (scalar): w = h2 @ W_c2 [HID x 4]; one dot per thread
    {
        int e = t >> 2, cc = t & 3;
        float a = 0.0f;
        #pragma unroll 8
        for (int k = 0; k < HID; k++)
            a = fmaf(h2S[e * PAD_H + k], W_c2[k * 4 + cc], a);
        wsS[e * 4 + cc] = a;
    }
    __syncthreads();

    // coord scatter
    float* aggc = g_agg_c + (size_t)b * NNODES * 12;
    for (int i = t; i < MT * 12; i += 256) {
        int e = i / 12, cc = i % 12;
        atomicAdd(&aggc[rows_s[e] * 12 + cc], cds[e * 12 + cc] * wsS[e * 4 + cc / 3]);
    }
}

// ---------------- node MLP (fp32 scalar) + coord update ----------------
__global__ __launch_bounds__(128) void node_kernel(
    const float* __restrict__ h, const float* __restrict__ coord,
    const float* __restrict__ W_n1, const float* __restrict__ b_n1,
    const float* __restrict__ W_n2, const float* __restrict__ b_n2,
    float* __restrict__ out)
{
    __shared__ float zs[NPB][2 * FIN];
    __shared__ float h1s[NPB][HID];

    const int t  = threadIdx.x;
    const int n0 = blockIdx.x * NPB;
    const int b  = blockIdx.y;
    const float* hb   = h + (size_t)b * NNODES * FIN;
    const float* aggh = g_agg_h + (size_t)b * NNODES * HID;

    #pragma unroll
    for (int e = 0; e < NPB; e++) {
        zs[e][t]       = hb[(n0 + e) * FIN + t];
        zs[e][FIN + t] = aggh[(n0 + e) * HID + t];
    }
    __syncthreads();

    float acc[NPB];
    {
        float bj = b_n1[t];
        #pragma unroll
        for (int e = 0; e < NPB; e++) acc[e] = bj;
        for (int k = 0; k < 2 * FIN; k += 4) {
            float w0 = W_n1[(k + 0) * HID + t];
            float w1 = W_n1[(k + 1) * HID + t];
            float w2 = W_n1[(k + 2) * HID + t];
            float w3 = W_n1[(k + 3) * HID + t];
            #pragma unroll
            for (int e = 0; e < NPB; e++) {
                float4 x4 = *(const float4*)&zs[e][k];
                acc[e] = fmaf(x4.x, w0, fmaf(x4.y, w1, fmaf(x4.z, w2, fmaf(x4.w, w3, acc[e]))));
            }
        }
        #pragma unroll
        for (int e = 0; e < NPB; e++) h1s[e][t] = fmaxf(acc[e], 0.0f);
    }
    __syncthreads();
    {
        float bj = b_n2[t];
        #pragma unroll
        for (int e = 0; e < NPB; e++) acc[e] = bj;
        for (int k = 0; k < HID; k += 4) {
            float w0 = W_n2[(k + 0) * FIN + t];
            float w1 = W_n2[(k + 1) * FIN + t];
            float w2 = W_n2[(k + 2) * FIN + t];
            float w3 = W_n2[(k + 3) * FIN + t];
            #pragma unroll
            for (int e = 0; e < NPB; e++) {
                float4 x4 = *(const float4*)&h1s[e][k];
                acc[e] = fmaf(x4.x, w0, fmaf(x4.y, w1, fmaf(x4.z, w2, fmaf(x4.w, w3, acc[e]))));
            }
        }
    }

    float* outh = out + (size_t)b * NNODES * FIN;
    #pragma unroll
    for (int e = 0; e < NPB; e++)
        outh[(n0 + e) * FIN + t] = zs[e][t] + acc[e];

    float* outc = out + (size_t)NB * NNODES * FIN + (size_t)b * NNODES * 12;
    const float* cb   = coord + (size_t)b * NNODES * 12;
    const float* aggc = g_agg_c + (size_t)b * NNODES * 12;
    for (int i = t; i < NPB * 12; i += 128) {
        int e = i / 12, cc = i % 12;
        int n = n0 + e;
        float cnt = fmaxf(g_cnt[n], 1.0f);
        outc[n * 12 + cc] = cb[n * 12 + cc] + aggc[n * 12 + cc] / cnt;
    }
}

extern "C" void kernel_launch(void* const* d_in, const int* in_sizes, int n_in,
                              void* d_out, int out_size)
{
    const float* h         = (const float*)d_in[0];
    const float* coord     = (const float*)d_in[1];
    const int*   edge_index= (const int*)  d_in[2];
    const float* edge_attr = (const float*)d_in[3];
    const float* W_e1 = (const float*)d_in[4];
    const float* b_e1 = (const float*)d_in[5];
    const float* W_e2 = (const float*)d_in[6];
    const float* b_e2 = (const float*)d_in[7];
    const float* W_n1 = (const float*)d_in[8];
    const float* b_n1 = (const float*)d_in[9];
    const float* W_n2 = (const float*)d_in[10];
    const float* b_n2 = (const float*)d_in[11];
    const float* W_c1 = (const float*)d_in[12];
    const float* b_c1 = (const float*)d_in[13];
    const float* W_c2 = (const float*)d_in[14];
    float* out = (float*)d_out;

    cudaFuncSetAttribute(edge_kernel,
                         cudaFuncAttributeMaxDynamicSharedMemorySize, SMEM_BYTES);

    prep_kernel<<<(INE * HID + 255) / 256, 256>>>(W_e1, W_e2, W_c1);
    zero_kernel<<<1024, 256>>>();
    count_kernel<<<(NEDGES + 255) / 256, 256>>>(edge_index);
    edge_kernel<<<dim3(NEDGES / MT, NB), 256, SMEM_BYTES>>>(
        h, coord, edge_index, edge_attr, b_e1, b_e2, b_c1, W_c2);
    node_kernel<<<dim3(NNODES / NPB, NB), 128>>>(
        h, coord, W_n1, b_n1, W_n2, b_n2, out);
}

// round 11
// speedup vs baseline: 1.0933x; 1.0933x over previous
#include <cuda_runtime.h>
#include <cstdint>

#define NB 2
#define NNODES 5000
#define NEDGES 160000
#define FIN 128
#define HID 128
#define ED 16
#define INE 288          // 2*FIN + 16 + ED
#define MT 64            // edges per block
#define PAD_X 164        // phase-buffer stride (mod 32 == 4 -> conflict-free A frags)
#define PAD_H 132        // hidden stride (mod 32 == 4)
#define KCH 16           // k-chunk per pipeline stage
#define BSTR 136         // B stage row stride (mod 32 == 8 -> conflict-free B frags)
#define BSF (KCH * BSTR) // floats per B stage buffer
#define NPB 8

// ---------------- scratch (allocation-free) ----------------
__device__ float g_agg_h[NB * NNODES * HID];
__device__ float g_agg_c[NB * NNODES * 12];
__device__ float g_cnt[NNODES];
__device__ __align__(16) float g_We1[INE * HID];
__device__ __align__(16) float g_We2[HID * HID];
__device__ __align__(16) float g_Wc1[HID * HID];

__device__ __forceinline__ float tf32r(float x) {
    uint32_t u;
    asm("cvt.rna.tf32.f32 %0, %1;" : "=r"(u) : "f"(x));
    return __uint_as_float(u);
}

__device__ __forceinline__ void mma_tf32(float c[4], uint32_t a0, uint32_t a1,
                                         uint32_t a2, uint32_t a3,
                                         uint32_t b0, uint32_t b1) {
    asm volatile(
        "mma.sync.aligned.m16n8k8.row.col.f32.tf32.tf32.f32 "
        "{%0,%1,%2,%3},{%4,%5,%6,%7},{%8,%9},{%0,%1,%2,%3};"
        : "+f"(c[0]), "+f"(c[1]), "+f"(c[2]), "+f"(c[3])
        : "r"(a0), "r"(a1), "r"(a2), "r"(a3), "r"(b0), "r"(b1));
}

__device__ __forceinline__ uint32_t smem_u32(const void* p) {
    return (uint32_t)__cvta_generic_to_shared(p);
}
#define CPA16(d, s) asm volatile("cp.async.ca.shared.global [%0], [%1], 16;" :: "r"(d), "l"(s) : "memory")
#define CPC()       asm volatile("cp.async.commit_group;" ::: "memory")
#define CPW(n)      asm volatile("cp.async.wait_group %0;" :: "n"(n) : "memory")

// ---------------- helper kernels ----------------
__global__ void zero_kernel() {
    const int T1 = NB * NNODES * HID;
    const int T2 = T1 + NB * NNODES * 12;
    const int total = T2 + NNODES;
    for (int i = blockIdx.x * blockDim.x + threadIdx.x; i < total;
         i += gridDim.x * blockDim.x) {
        if (i < T1)       g_agg_h[i] = 0.0f;
        else if (i < T2)  g_agg_c[i - T1] = 0.0f;
        else              g_cnt[i - T2] = 0.0f;
    }
}

__global__ void count_kernel(const int* __restrict__ edge_index) {
    int e = blockIdx.x * blockDim.x + threadIdx.x;
    if (e < NEDGES) atomicAdd(&g_cnt[edge_index[e]], 1.0f);
}

__global__ void prep_kernel(const float* __restrict__ W_e1,
                            const float* __restrict__ W_e2,
                            const float* __restrict__ W_c1) {
    int i = blockIdx.x * blockDim.x + threadIdx.x;
    if (i < INE * HID) g_We1[i] = tf32r(W_e1[i]);
    if (i < HID * HID) {
        g_We2[i] = tf32r(W_e2[i]);
        g_Wc1[i] = tf32r(W_c1[i]);
    }
}

__device__ __forceinline__ void init_c(const float* __restrict__ bias,
                                       int n_base, int tig, float c[2][4][4]) {
    #pragma unroll
    for (int nj = 0; nj < 4; nj++) {
        float bv0 = bias[n_base + nj * 8 + 2 * tig];
        float bv1 = bias[n_base + nj * 8 + 2 * tig + 1];
        #pragma unroll
        for (int mi = 0; mi < 2; mi++) {
            c[mi][nj][0] = bv0; c[mi][nj][1] = bv1;
            c[mi][nj][2] = bv0; c[mi][nj][3] = bv1;
        }
    }
}

// ------- block-wide 2-stage cp.async weight pipeline GEMM -------
// NSTAGES stages of KCH=16 k. A from smem inS (stride PADIN, cols 0..16*NSTAGES),
// B streamed from Wg (row-major K x HID) into bst (2 stage buffers).
// Accumulates into c. Contains __syncthreads (uniform across block).
template<int NSTAGES, int PADIN>
__device__ __forceinline__ void mma_gemm_st(
    const float* __restrict__ inS, const float* __restrict__ Wg,
    float* __restrict__ bst, int t, int m_base, int n_base, int g, int tig,
    float c[2][4][4])
{
    const int lr = t >> 4;           // stage row 0..15
    const int lc = (t & 15) * 8;     // col 0,8,...,120
    {   // prologue: stage 0
        const float* src = Wg + lr * HID + lc;
        uint32_t d = smem_u32(bst + lr * BSTR + lc);
        CPA16(d, src); CPA16(d + 16, src + 4); CPC();
    }
    #pragma unroll
    for (int s = 0; s < NSTAGES; s++) {
        CPW(0);
        __syncthreads();              // stage s data visible; stage s-1 buffer free
        if (s + 1 < NSTAGES) {
            const float* src = Wg + ((s + 1) * KCH + lr) * HID + lc;
            uint32_t d = smem_u32(bst + ((s + 1) & 1) * BSF + lr * BSTR + lc);
            CPA16(d, src); CPA16(d + 16, src + 4); CPC();
        }
        const float* pan = bst + (s & 1) * BSF;
        #pragma unroll
        for (int ks = 0; ks < 2; ks++) {
            const int kg = s * KCH + ks * 8;
            uint32_t a[2][4];
            #pragma unroll
            for (int mi = 0; mi < 2; mi++) {
                const float* xr = inS + (m_base + mi * 16 + g) * PADIN + kg + tig;
                a[mi][0] = __float_as_uint(xr[0]);
                a[mi][1] = __float_as_uint(xr[8 * PADIN]);
                a[mi][2] = __float_as_uint(xr[4]);
                a[mi][3] = __float_as_uint(xr[8 * PADIN + 4]);
            }
            uint32_t b0[4], b1[4];
            #pragma unroll
            for (int nj = 0; nj < 4; nj++) {
                b0[nj] = __float_as_uint(pan[(ks * 8 + tig) * BSTR + n_base + nj * 8 + g]);
                b1[nj] = __float_as_uint(pan[(ks * 8 + tig + 4) * BSTR + n_base + nj * 8 + g]);
            }
            #pragma unroll
            for (int nj = 0; nj < 4; nj++)
                #pragma unroll
                for (int mi = 0; mi < 2; mi++)
                    mma_tf32(c[mi][nj], a[mi][0], a[mi][1], a[mi][2], a[mi][3],
                             b0[nj], b1[nj]);
        }
    }
}

// smem float offsets
#define OFF_XB  0                          // [MT][PAD_X] (aliased by efS)
#define OFF_H1  (MT * PAD_X)               // [MT][PAD_H] h1 (aliased by h2)
#define OFF_BS  (OFF_H1 + MT * PAD_H)      // 2 * BSF weight stages
#define OFF_CDS (OFF_BS + 2 * BSF)
#define OFF_WS  (OFF_CDS + MT * 12)
#define OFF_IDX (OFF_WS + MT * 4)
#define SMEM_FLOATS (OFF_IDX + 2 * MT)
#define SMEM_BYTES  (SMEM_FLOATS * 4)

__global__ __launch_bounds__(256, 2) void edge_kernel(
    const float* __restrict__ h, const float* __restrict__ coord,
    const int* __restrict__ edge_index, const float* __restrict__ edge_attr,
    const float* __restrict__ b_e1, const float* __restrict__ b_e2,
    const float* __restrict__ b_c1, const float* __restrict__ W_c2)
{
    extern __shared__ float sm[];
    float* xb   = sm + OFF_XB;
    float* efS  = sm + OFF_XB;    // alias (xb dead after GEMM1)
    float* h1S  = sm + OFF_H1;
    float* h2S  = sm + OFF_H1;    // alias (h1 dead after GEMM2)
    float* bst  = sm + OFF_BS;
    float* cds  = sm + OFF_CDS;
    float* wsS  = sm + OFF_WS;
    int* rows_s = (int*)(sm + OFF_IDX);
    int* cols_s = rows_s + MT;

    const int t    = threadIdx.x;
    const int lane = t & 31;
    const int w    = t >> 5;
    const int g    = lane >> 2;
    const int tig  = lane & 3;
    const int m_base = (w >> 2) * 32;   // 2 m-warps
    const int n_base = (w & 3) * 32;    // 4 n-warps

    const int e0 = blockIdx.x * MT;
    const int b  = blockIdx.y;
    const float* hb = h + (size_t)b * NNODES * FIN;
    const float* cb = coord + (size_t)b * NNODES * 12;

    if (t < MT) {
        rows_s[t] = edge_index[e0 + t];
        cols_s[t] = edge_index[NEDGES + e0 + t];
    }
    __syncthreads();

    // ---- phase A fill: h[row] into cols [0,128); cds ----
    for (int i = t; i < MT * FIN; i += 256) {
        int e = i >> 7, k = i & 127;
        xb[e * PAD_X + k] = tf32r(hb[rows_s[e] * FIN + k]);
    }
    for (int i = t; i < MT * 12; i += 256) {
        int e = i / 12, c = i % 12;
        cds[e * 12 + c] = cb[rows_s[e] * 12 + c] - cb[cols_s[e] * 12 + c];
    }
    __syncthreads();

    float c[2][4][4];
    init_c(b_e1, n_base, tig, c);
    // GEMM1 phase A: We1 rows 0..127
    mma_gemm_st<8, PAD_X>(xb, g_We1, bst, t, m_base, n_base, g, tig, c);
    __syncthreads();   // all warps done reading xb

    // ---- phase B fill: h[col] [0,128), radial [128,144), attr [144,160) ----
    for (int i = t; i < MT * FIN; i += 256) {
        int e = i >> 7, k = i & 127;
        xb[e * PAD_X + k] = tf32r(hb[cols_s[e] * FIN + k]);
    }
    for (int i = t; i < MT * ED; i += 256) {
        int e = i >> 4, cc = i & 15;
        xb[e * PAD_X + 144 + cc] = tf32r(edge_attr[(size_t)(e0 + e) * ED + cc]);
    }
    if (t < MT) {
        float cd[12];
        #pragma unroll
        for (int cc = 0; cc < 12; cc++) cd[cc] = cds[t * 12 + cc];
        float prod[16], ss = 0.0f;
        #pragma unroll
        for (int j = 0; j < 4; j++)
            #pragma unroll
            for (int k = 0; k < 4; k++) {
                float p = cd[j*3]*cd[k*3] + cd[j*3+1]*cd[k*3+1] + cd[j*3+2]*cd[k*3+2];
                prod[j * 4 + k] = p;
                ss += p * p;
            }
        float inv = 1.0f / fmaxf(sqrtf(ss), 1e-12f);
        #pragma unroll
        for (int i = 0; i < 16; i++)
            xb[t * PAD_X + 128 + i] = tf32r(prod[i] * inv);
    }
    __syncthreads();

    // GEMM1 phase B: We1 rows 128..287 (local k 0..159), accumulate
    mma_gemm_st<10, PAD_X>(xb, g_We1 + 128 * HID, bst, t, m_base, n_base, g, tig, c);

    // h1 = tf32(relu(c))  (h1 region not read by anyone during GEMM1 -> safe)
    #pragma unroll
    for (int nj = 0; nj < 4; nj++) {
        int col = n_base + nj * 8 + 2 * tig;
        #pragma unroll
        for (int mi = 0; mi < 2; mi++) {
            int r = m_base + mi * 16 + g;
            h1S[r * PAD_H + col]           = tf32r(fmaxf(c[mi][nj][0], 0.0f));
            h1S[r * PAD_H + col + 1]       = tf32r(fmaxf(c[mi][nj][1], 0.0f));
            h1S[(r + 8) * PAD_H + col]     = tf32r(fmaxf(c[mi][nj][2], 0.0f));
            h1S[(r + 8) * PAD_H + col + 1] = tf32r(fmaxf(c[mi][nj][3], 0.0f));
        }
    }
    __syncthreads();

    // GEMM2: h1 @ We2 -> relu -> ef (xb region, not read during GEMM2) ; scatter agg_h
    init_c(b_e2, n_base, tig, c);
    mma_gemm_st<8, PAD_H>(h1S, g_We2, bst, t, m_base, n_base, g, tig, c);
    {
        float* aggh = g_agg_h + (size_t)b * NNODES * HID;
        #pragma unroll
        for (int nj = 0; nj < 4; nj++) {
            int col = n_base + nj * 8 + 2 * tig;
            #pragma unroll
            for (int mi = 0; mi < 2; mi++) {
                int r = m_base + mi * 16 + g;
                float v0 = fmaxf(c[mi][nj][0], 0.0f), v1 = fmaxf(c[mi][nj][1], 0.0f);
                float v2 = fmaxf(c[mi][nj][2], 0.0f), v3 = fmaxf(c[mi][nj][3], 0.0f);
                efS[r * PAD_H + col]           = tf32r(v0);
                efS[r * PAD_H + col + 1]       = tf32r(v1);
                efS[(r + 8) * PAD_H + col]     = tf32r(v2);
                efS[(r + 8) * PAD_H + col + 1] = tf32r(v3);
                atomicAdd(&aggh[rows_s[r] * HID + col],         v0);
                atomicAdd(&aggh[rows_s[r] * HID + col + 1],     v1);
                atomicAdd(&aggh[rows_s[r + 8] * HID + col],     v2);
                atomicAdd(&aggh[rows_s[r + 8] * HID + col + 1], v3);
            }
        }
    }
    __syncthreads();

    // GEMM3: ef @ Wc1 -> relu -> h2 (h1 region, not read during GEMM3)
    init_c(b_c1, n_base, tig, c);
    mma_gemm_st<8, PAD_H>(efS, g_Wc1, bst, t, m_base, n_base, g, tig, c);
    #pragma unroll
    for (int nj = 0; nj < 4; nj++) {
        int col = n_base + nj * 8 + 2 * tig;
        #pragma unroll
        for (int mi = 0; mi < 2; mi++) {
            int r = m_base + mi * 16 + g;
            h2S[r * PAD_H + col]           = fmaxf(c[mi][nj][0], 0.0f);
            h2S[r * PAD_H + col + 1]       = fmaxf(c[mi][nj][1], 0.0f);
            h2S[(r + 8) * PAD_H + col]     = fmaxf(c[mi][nj][2], 0.0f);
            h2S[(r + 8) * PAD_H + col + 1] = fmaxf(c[mi][nj][3], 0.0f);
        }
    }
    __syncthreads();

    // GEMM4 (scalar): w = h2 @ W_c2 [HID x 4]; one dot per thread
    {
        int e = t >> 2, cc = t & 3;
        float a = 0.0f;
        #pragma unroll 8
        for (int k = 0; k < HID; k++)
            a = fmaf(h2S[e * PAD_H + k], W_c2[k * 4 + cc], a);
        wsS[e * 4 + cc] = a;
    }
    __syncthreads();

    // coord scatter
    float* aggc = g_agg_c + (size_t)b * NNODES * 12;
    for (int i = t; i < MT * 12; i += 256) {
        int e = i / 12, cc = i % 12;
        atomicAdd(&aggc[rows_s[e] * 12 + cc], cds[e * 12 + cc] * wsS[e * 4 + cc / 3]);
    }
}

// ---------------- node MLP (fp32 scalar) + coord update ----------------
__global__ __launch_bounds__(128) void node_kernel(
    const float* __restrict__ h, const float* __restrict__ coord,
    const float* __restrict__ W_n1, const float* __restrict__ b_n1,
    const float* __restrict__ W_n2, const float* __restrict__ b_n2,
    float* __restrict__ out)
{
    __shared__ float zs[NPB][2 * FIN];
    __shared__ float h1s[NPB][HID];

    const int t  = threadIdx.x;
    const int n0 = blockIdx.x * NPB;
    const int b  = blockIdx.y;
    const float* hb   = h + (size_t)b * NNODES * FIN;
    const float* aggh = g_agg_h + (size_t)b * NNODES * HID;

    #pragma unroll
    for (int e = 0; e < NPB; e++) {
        zs[e][t]       = hb[(n0 + e) * FIN + t];
        zs[e][FIN + t] = aggh[(n0 + e) * HID + t];
    }
    __syncthreads();

    float acc[NPB];
    {
        float bj = b_n1[t];
        #pragma unroll
        for (int e = 0; e < NPB; e++) acc[e] = bj;
        for (int k = 0; k < 2 * FIN; k += 4) {
            float w0 = W_n1[(k + 0) * HID + t];
            float w1 = W_n1[(k + 1) * HID + t];
            float w2 = W_n1[(k + 2) * HID + t];
            float w3 = W_n1[(k + 3) * HID + t];
            #pragma unroll
            for (int e = 0; e < NPB; e++) {
                float4 x4 = *(const float4*)&zs[e][k];
                acc[e] = fmaf(x4.x, w0, fmaf(x4.y, w1, fmaf(x4.z, w2, fmaf(x4.w, w3, acc[e]))));
            }
        }
        #pragma unroll
        for (int e = 0; e < NPB; e++) h1s[e][t] = fmaxf(acc[e], 0.0f);
    }
    __syncthreads();
    {
        float bj = b_n2[t];
        #pragma unroll
        for (int e = 0; e < NPB; e++) acc[e] = bj;
        for (int k = 0; k < HID; k += 4) {
            float w0 = W_n2[(k + 0) * FIN + t];
            float w1 = W_n2[(k + 1) * FIN + t];
            float w2 = W_n2[(k + 2) * FIN + t];
            float w3 = W_n2[(k + 3) * FIN + t];
            #pragma unroll
            for (int e = 0; e < NPB; e++) {
                float4 x4 = *(const float4*)&h1s[e][k];
                acc[e] = fmaf(x4.x, w0, fmaf(x4.y, w1, fmaf(x4.z, w2, fmaf(x4.w, w3, acc[e]))));
            }
        }
    }

    float* outh = out + (size_t)b * NNODES * FIN;
    #pragma unroll
    for (int e = 0; e < NPB; e++)
        outh[(n0 + e) * FIN + t] = zs[e][t] + acc[e];

    float* outc = out + (size_t)NB * NNODES * FIN + (size_t)b * NNODES * 12;
    const float* cb   = coord + (size_t)b * NNODES * 12;
    const float* aggc = g_agg_c + (size_t)b * NNODES * 12;
    for (int i = t; i < NPB * 12; i += 128) {
        int e = i / 12, cc = i % 12;
        int n = n0 + e;
        float cnt = fmaxf(g_cnt[n], 1.0f);
        outc[n * 12 + cc] = cb[n * 12 + cc] + aggc[n * 12 + cc] / cnt;
    }
}

extern "C" void kernel_launch(void* const* d_in, const int* in_sizes, int n_in,
                              void* d_out, int out_size)
{
    const float* h         = (const float*)d_in[0];
    const float* coord     = (const float*)d_in[1];
    const int*   edge_index= (const int*)  d_in[2];
    const float* edge_attr = (const float*)d_in[3];
    const float* W_e1 = (const float*)d_in[4];
    const float* b_e1 = (const float*)d_in[5];
    const float* W_e2 = (const float*)d_in[6];
    const float* b_e2 = (const float*)d_in[7];
    const float* W_n1 = (const float*)d_in[8];
    const float* b_n1 = (const float*)d_in[9];
    const float* W_n2 = (const float*)d_in[10];
    const float* b_n2 = (const float*)d_in[11];
    const float* W_c1 = (const float*)d_in[12];
    const float* b_c1 = (const float*)d_in[13];
    const float* W_c2 = (const float*)d_in[14];
    float* out = (float*)d_out;

    cudaFuncSetAttribute(edge_kernel,
                         cudaFuncAttributeMaxDynamicSharedMemorySize, SMEM_BYTES);

    prep_kernel<<<(INE * HID + 255) / 256, 256>>>(W_e1, W_e2, W_c1);
    zero_kernel<<<1024, 256>>>();
    count_kernel<<<(NEDGES + 255) / 256, 256>>>(edge_index);
    edge_kernel<<<dim3(NEDGES / MT, NB), 256, SMEM_BYTES>>>(
        h, coord, edge_index, edge_attr, b_e1, b_e2, b_c1, W_c2);
    node_kernel<<<dim3(NNODES / NPB, NB), 128>>>(
        h, coord, W_n1, b_n1, W_n2, b_n2, out);
}

// round 14
// speedup vs baseline: 1.1374x; 1.0403x over previous
#include <cuda_runtime.h>
#include <cstdint>

#define NB 2
#define NNODES 5000
#define NEDGES 160000
#define FIN 128
#define HID 128
#define ED 16
#define INE 288          // 2*FIN + 16 + ED
#define MT 64            // edges per block
#define PAD_H 132        // activation stride (mod 32 == 4 -> conflict-free A frags)
#define KCH 32           // k-chunk per pipeline stage
#define BSTR 136         // B stage row stride (mod 32 == 8 -> conflict-free B frags)
#define BSF (KCH * BSTR) // floats per B stage buffer (4352)
#define NPB 8

// ---------------- scratch (allocation-free) ----------------
__device__ float g_agg_h[NB * NNODES * HID];
__device__ float g_agg_c[NB * NNODES * 12];
__device__ float g_cnt[NNODES];
__device__ __align__(16) float g_We1[INE * HID];
__device__ __align__(16) float g_We2[HID * HID];
__device__ __align__(16) float g_Wc1[HID * HID];

__device__ __forceinline__ float tf32r(float x) {
    uint32_t u;
    asm("cvt.rna.tf32.f32 %0, %1;" : "=r"(u) : "f"(x));
    return __uint_as_float(u);
}

__device__ __forceinline__ void mma_tf32(float c[4], uint32_t a0, uint32_t a1,
                                         uint32_t a2, uint32_t a3,
                                         uint32_t b0, uint32_t b1) {
    asm volatile(
        "mma.sync.aligned.m16n8k8.row.col.f32.tf32.tf32.f32 "
        "{%0,%1,%2,%3},{%4,%5,%6,%7},{%8,%9},{%0,%1,%2,%3};"
        : "+f"(c[0]), "+f"(c[1]), "+f"(c[2]), "+f"(c[3])
        : "r"(a0), "r"(a1), "r"(a2), "r"(a3), "r"(b0), "r"(b1));
}

__device__ __forceinline__ uint32_t smem_u32(const void* p) {
    return (uint32_t)__cvta_generic_to_shared(p);
}
#define CPA16(d, s) asm volatile("cp.async.ca.shared.global [%0], [%1], 16;" :: "r"(d), "l"(s) : "memory")
#define CPC()       asm volatile("cp.async.commit_group;" ::: "memory")
#define CPW(n)      asm volatile("cp.async.wait_group %0;" :: "n"(n) : "memory")

// ---------------- helper kernels ----------------
__global__ void zero_kernel() {
    const int T1 = NB * NNODES * HID;
    const int T2 = T1 + NB * NNODES * 12;
    const int total = T2 + NNODES;
    for (int i = blockIdx.x * blockDim.x + threadIdx.x; i < total;
         i += gridDim.x * blockDim.x) {
        if (i < T1)       g_agg_h[i] = 0.0f;
        else if (i < T2)  g_agg_c[i - T1] = 0.0f;
        else              g_cnt[i - T2] = 0.0f;
    }
}

__global__ void count_kernel(const int* __restrict__ edge_index) {
    int e = blockIdx.x * blockDim.x + threadIdx.x;
    if (e < NEDGES) atomicAdd(&g_cnt[edge_index[e]], 1.0f);
}

__global__ void prep_kernel(const float* __restrict__ W_e1,
                            const float* __restrict__ W_e2,
                            const float* __restrict__ W_c1) {
    int i = blockIdx.x * blockDim.x + threadIdx.x;
    if (i < INE * HID) g_We1[i] = tf32r(W_e1[i]);
    if (i < HID * HID) {
        g_We2[i] = tf32r(W_e2[i]);
        g_Wc1[i] = tf32r(W_c1[i]);
    }
}

__device__ __forceinline__ void init_c(const float* __restrict__ bias,
                                       int n_base, int tig, float c[2][4][4]) {
    #pragma unroll
    for (int nj = 0; nj < 4; nj++) {
        float bv0 = bias[n_base + nj * 8 + 2 * tig];
        float bv1 = bias[n_base + nj * 8 + 2 * tig + 1];
        #pragma unroll
        for (int mi = 0; mi < 2; mi++) {
            c[mi][nj][0] = bv0; c[mi][nj][1] = bv1;
            c[mi][nj][2] = bv0; c[mi][nj][3] = bv1;
        }
    }
}

// ------- block-wide 2-stage (KCH=32) cp.async weight pipeline GEMM -------
// A from smem inS (stride PAD_H); B streamed from Wg (row-major K x HID).
// Accumulates into c. Contains __syncthreads (uniform across block).
template<int NSTAGES>
__device__ __forceinline__ void mma_gemm_st(
    const float* __restrict__ inS, const float* __restrict__ Wg,
    float* __restrict__ bst, int t, int m_base, int n_base, int g, int tig,
    float c[2][4][4])
{
    const int lr = t >> 3;           // stage row 0..31
    const int lc = (t & 7) * 16;     // col 0,16,...,112
    {   // prologue: stage 0
        const float* src = Wg + lr * HID + lc;
        uint32_t d = smem_u32(bst + lr * BSTR + lc);
        CPA16(d, src); CPA16(d + 16, src + 4);
        CPA16(d + 32, src + 8); CPA16(d + 48, src + 12); CPC();
    }
    #pragma unroll
    for (int s = 0; s < NSTAGES; s++) {
        CPW(0);
        __syncthreads();              // stage s visible; all warps done with s-1
        if (s + 1 < NSTAGES) {
            const float* src = Wg + ((s + 1) * KCH + lr) * HID + lc;
            uint32_t d = smem_u32(bst + ((s + 1) & 1) * BSF + lr * BSTR + lc);
            CPA16(d, src); CPA16(d + 16, src + 4);
            CPA16(d + 32, src + 8); CPA16(d + 48, src + 12); CPC();
        }
        const float* pan = bst + (s & 1) * BSF;
        #pragma unroll
        for (int ks = 0; ks < 4; ks++) {
            const int kg = s * KCH + ks * 8;
            uint32_t a[2][4];
            #pragma unroll
            for (int mi = 0; mi < 2; mi++) {
                const float* xr = inS + (m_base + mi * 16 + g) * PAD_H + kg + tig;
                a[mi][0] = __float_as_uint(xr[0]);
                a[mi][1] = __float_as_uint(xr[8 * PAD_H]);
                a[mi][2] = __float_as_uint(xr[4]);
                a[mi][3] = __float_as_uint(xr[8 * PAD_H + 4]);
            }
            uint32_t b0[4], b1[4];
            #pragma unroll
            for (int nj = 0; nj < 4; nj++) {
                b0[nj] = __float_as_uint(pan[(ks * 8 + tig) * BSTR + n_base + nj * 8 + g]);
                b1[nj] = __float_as_uint(pan[(ks * 8 + tig + 4) * BSTR + n_base + nj * 8 + g]);
            }
            #pragma unroll
            for (int nj = 0; nj < 4; nj++)
                #pragma unroll
                for (int mi = 0; mi < 2; mi++)
                    mma_tf32(c[mi][nj], a[mi][0], a[mi][1], a[mi][2], a[mi][3],
                             b0[nj], b1[nj]);
        }
    }
}

// smem float offsets
#define OFF_A   0                          // bufA [MT][PAD_H]: h[row] -> h1 -> h2
#define OFF_B   (MT * PAD_H)               // bufB [MT][PAD_H]: h[col] -> rad/attr -> ef
#define OFF_BS  (OFF_B + MT * PAD_H)       // 2 * BSF weight stages (wsS overlaid)
#define OFF_CDS (OFF_BS + 2 * BSF)
#define OFF_IDX (OFF_CDS + MT * 12)
#define SMEM_FLOATS (OFF_IDX + 2 * MT)
#define SMEM_BYTES  (SMEM_FLOATS * 4)

__global__ __launch_bounds__(256, 2) void edge_kernel(
    const float* __restrict__ h, const float* __restrict__ coord,
    const int* __restrict__ edge_index, const float* __restrict__ edge_attr,
    const float* __restrict__ b_e1, const float* __restrict__ b_e2,
    const float* __restrict__ b_c1, const float* __restrict__ W_c2)
{
    extern __shared__ float sm[];
    float* bufA = sm + OFF_A;
    float* bufB = sm + OFF_B;
    float* bst  = sm + OFF_BS;
    float* wsS  = sm + OFF_BS;    // overlaid: bst dead when wsS is live
    float* cds  = sm + OFF_CDS;
    int* rows_s = (int*)(sm + OFF_IDX);
    int* cols_s = rows_s + MT;

    const int t    = threadIdx.x;
    const int lane = t & 31;
    const int w    = t >> 5;
    const int g    = lane >> 2;
    const int tig  = lane & 3;
    const int m_base = (w >> 2) * 32;   // 2 m-warps
    const int n_base = (w & 3) * 32;    // 4 n-warps

    const int e0 = blockIdx.x * MT;
    const int b  = blockIdx.y;
    const float* hb = h + (size_t)b * NNODES * FIN;
    const float* cb = coord + (size_t)b * NNODES * 12;

    if (t < MT) {
        rows_s[t] = edge_index[e0 + t];
        cols_s[t] = edge_index[NEDGES + e0 + t];
    }
    __syncthreads();

    const int fe = t >> 2, fq = t & 3;   // fill mapping: 64 edges x 4 chunks

    // ---- fill bufA = h[row] via cp.async (HW truncates to tf32 in mma) ----
    {
        const float* src = hb + (size_t)rows_s[fe] * FIN + fq * 32;
        uint32_t d = smem_u32(bufA + fe * PAD_H + fq * 32);
        #pragma unroll
        for (int j = 0; j < 8; j++) CPA16(d + j * 16, src + j * 4);
        CPC();
    }
    // cds (plain loads)
    for (int i = t; i < MT * 12; i += 256) {
        int e = i / 12, cc = i % 12;
        cds[e * 12 + cc] = cb[rows_s[e] * 12 + cc] - cb[cols_s[e] * 12 + cc];
    }

    float c[2][4][4];
    init_c(b_e1, n_base, tig, c);
    // GEMM1 phase A: We1 rows 0..127  (iter-0 CPW+barrier also covers bufA fill)
    mma_gemm_st<4>(bufA, g_We1, bst, t, m_base, n_base, g, tig, c);

    // ---- fill bufB = h[col] (disjoint from bufA/bst reads of lagging warps) ----
    {
        const float* src = hb + (size_t)cols_s[fe] * FIN + fq * 32;
        uint32_t d = smem_u32(bufB + fe * PAD_H + fq * 32);
        #pragma unroll
        for (int j = 0; j < 8; j++) CPA16(d + j * 16, src + j * 4);
        CPC();
    }
    // GEMM1 phase B: We1 rows 128..255
    mma_gemm_st<4>(bufB, g_We1 + 128 * HID, bst, t, m_base, n_base, g, tig, c);

    // ---- fill bufB cols 0..15 = radial, 16..31 = attr (disjoint from lagging
    //      phase-B reads, which touch cols 96..127 at worst) ----
    {
        const float* src = edge_attr + (size_t)(e0 + fe) * ED + fq * 4;
        uint32_t d = smem_u32(bufB + fe * PAD_H + 16 + fq * 4);
        CPA16(d, src); CPC();
    }
    if (t < MT) {
        float cd[12];
        #pragma unroll
        for (int cc = 0; cc < 12; cc++) cd[cc] = cds[t * 12 + cc];
        float prod[16], ss = 0.0f;
        #pragma unroll
        for (int j = 0; j < 4; j++)
            #pragma unroll
            for (int k = 0; k < 4; k++) {
                float p = cd[j*3]*cd[k*3] + cd[j*3+1]*cd[k*3+1] + cd[j*3+2]*cd[k*3+2];
                prod[j * 4 + k] = p;
                ss += p * p;
            }
        float inv = 1.0f / fmaxf(sqrtf(ss), 1e-12f);
        #pragma unroll
        for (int i = 0; i < 16; i++)
            bufB[t * PAD_H + i] = tf32r(prod[i] * inv);
    }
    // GEMM1 phase C: We1 rows 256..287 (1 stage; internal barrier orders fills)
    mma_gemm_st<1>(bufB, g_We1 + 256 * HID, bst, t, m_base, n_base, g, tig, c);

    // h1 = tf32(relu(c)) -> bufA (bufA dead since phase A; writes disjoint from
    // lagging phase-C reads of bufB)
    #pragma unroll
    for (int nj = 0; nj < 4; nj++) {
        int col = n_base + nj * 8 + 2 * tig;
        #pragma unroll
        for (int mi = 0; mi < 2; mi++) {
            int r = m_base + mi * 16 + g;
            bufA[r * PAD_H + col]           = tf32r(fmaxf(c[mi][nj][0], 0.0f));
            bufA[r * PAD_H + col + 1]       = tf32r(fmaxf(c[mi][nj][1], 0.0f));
            bufA[(r + 8) * PAD_H + col]     = tf32r(fmaxf(c[mi][nj][2], 0.0f));
            bufA[(r + 8) * PAD_H + col + 1] = tf32r(fmaxf(c[mi][nj][3], 0.0f));
        }
    }
    __syncthreads();   // REQUIRED: GEMM2 prologue overwrites buf0 still read by phase C

    // GEMM2: h1 @ We2 -> relu -> ef (bufB) ; scatter agg_h from fp32 accums
    init_c(b_e2, n_base, tig, c);
    mma_gemm_st<4>(bufA, g_We2, bst, t, m_base, n_base, g, tig, c);
    {
        float* aggh = g_agg_h + (size_t)b * NNODES * HID;
        #pragma unroll
        for (int nj = 0; nj < 4; nj++) {
            int col = n_base + nj * 8 + 2 * tig;
            #pragma unroll
            for (int mi = 0; mi < 2; mi++) {
                int r = m_base + mi * 16 + g;
                float v0 = fmaxf(c[mi][nj][0], 0.0f), v1 = fmaxf(c[mi][nj][1], 0.0f);
                float v2 = fmaxf(c[mi][nj][2], 0.0f), v3 = fmaxf(c[mi][nj][3], 0.0f);
                bufB[r * PAD_H + col]           = tf32r(v0);
                bufB[r * PAD_H + col + 1]       = tf32r(v1);
                bufB[(r + 8) * PAD_H + col]     = tf32r(v2);
                bufB[(r + 8) * PAD_H + col + 1] = tf32r(v3);
                atomicAdd(&aggh[rows_s[r] * HID + col],         v0);
                atomicAdd(&aggh[rows_s[r] * HID + col + 1],     v1);
                atomicAdd(&aggh[rows_s[r + 8] * HID + col],     v2);
                atomicAdd(&aggh[rows_s[r + 8] * HID + col + 1], v3);
            }
        }
    }
    // (no explicit barrier needed: GEMM3 prologue targets buf0, last read at
    //  GEMM2 stage 2, fenced by stage-3 entry barrier; ef STS ordered by GEMM3's
    //  internal iter-0 barrier)

    // GEMM3: ef @ Wc1 -> relu -> h2 (bufA)
    init_c(b_c1, n_base, tig, c);
    mma_gemm_st<4>(bufB, g_Wc1, bst, t, m_base, n_base, g, tig, c);
    #pragma unroll
    for (int nj = 0; nj < 4; nj++) {
        int col = n_base + nj * 8 + 2 * tig;
        #pragma unroll
        for (int mi = 0; mi < 2; mi++) {
            int r = m_base + mi * 16 + g;
            bufA[r * PAD_H + col]           = fmaxf(c[mi][nj][0], 0.0f);
            bufA[r * PAD_H + col + 1]       = fmaxf(c[mi][nj][1], 0.0f);
            bufA[(r + 8) * PAD_H + col]     = fmaxf(c[mi][nj][2], 0.0f);
            bufA[(r + 8) * PAD_H + col + 1] = fmaxf(c[mi][nj][3], 0.0f);
        }
    }
    __syncthreads();   // REQUIRED: wsS overlays bst; all warps must be past GEMM3

    // GEMM4 (scalar): w = h2 @ W_c2 [HID x 4]; one dot per thread
    {
        int e = t >> 2, cc = t & 3;
        float a = 0.0f;
        #pragma unroll 8
        for (int k = 0; k < HID; k++)
            a = fmaf(bufA[e * PAD_H + k], W_c2[k * 4 + cc], a);
        wsS[e * 4 + cc] = a;
    }
    __syncthreads();

    // coord scatter
    float* aggc = g_agg_c + (size_t)b * NNODES * 12;
    for (int i = t; i < MT * 12; i += 256) {
        int e = i / 12, cc = i % 12;
        atomicAdd(&aggc[rows_s[e] * 12 + cc], cds[e * 12 + cc] * wsS[e * 4 + cc / 3]);
    }
}

// ---------------- node MLP (fp32 scalar) + coord update ----------------
__global__ __launch_bounds__(128) void node_kernel(
    const float* __restrict__ h, const float* __restrict__ coord,
    const float* __restrict__ W_n1, const float* __restrict__ b_n1,
    const float* __restrict__ W_n2, const float* __restrict__ b_n2,
    float* __restrict__ out)
{
    __shared__ float zs[NPB][2 * FIN];
    __shared__ float h1s[NPB][HID];

    const int t  = threadIdx.x;
    const int n0 = blockIdx.x * NPB;
    const int b  = blockIdx.y;
    const float* hb   = h + (size_t)b * NNODES * FIN;
    const float* aggh = g_agg_h + (size_t)b * NNODES * HID;

    #pragma unroll
    for (int e = 0; e < NPB; e++) {
        zs[e][t]       = hb[(n0 + e) * FIN + t];
        zs[e][FIN + t] = aggh[(n0 + e) * HID + t];
    }
    __syncthreads();

    float acc[NPB];
    {
        float bj = b_n1[t];
        #pragma unroll
        for (int e = 0; e < NPB; e++) acc[e] = bj;
        for (int k = 0; k < 2 * FIN; k += 4) {
            float w0 = W_n1[(k + 0) * HID + t];
            float w1 = W_n1[(k + 1) * HID + t];
            float w2 = W_n1[(k + 2) * HID + t];
            float w3 = W_n1[(k + 3) * HID + t];
            #pragma unroll
            for (int e = 0; e < NPB; e++) {
                float4 x4 = *(const float4*)&zs[e][k];
                acc[e] = fmaf(x4.x, w0, fmaf(x4.y, w1, fmaf(x4.z, w2, fmaf(x4.w, w3, acc[e]))));
            }
        }
        #pragma unroll
        for (int e = 0; e < NPB; e++) h1s[e][t] = fmaxf(acc[e], 0.0f);
    }
    __syncthreads();
    {
        float bj = b_n2[t];
        #pragma unroll
        for (int e = 0; e < NPB; e++) acc[e] = bj;
        for (int k = 0; k < HID; k += 4) {
            float w0 = W_n2[(k + 0) * FIN + t];
            float w1 = W_n2[(k + 1) * FIN + t];
            float w2 = W_n2[(k + 2) * FIN + t];
            float w3 = W_n2[(k + 3) * FIN + t];
            #pragma unroll
            for (int e = 0; e < NPB; e++) {
                float4 x4 = *(const float4*)&h1s[e][k];
                acc[e] = fmaf(x4.x, w0, fmaf(x4.y, w1, fmaf(x4.z, w2, fmaf(x4.w, w3, acc[e]))));
            }
        }
    }

    float* outh = out + (size_t)b * NNODES * FIN;
    #pragma unroll
    for (int e = 0; e < NPB; e++)
        outh[(n0 + e) * FIN + t] = zs[e][t] + acc[e];

    float* outc = out + (size_t)NB * NNODES * FIN + (size_t)b * NNODES * 12;
    const float* cb   = coord + (size_t)b * NNODES * 12;
    const float* aggc = g_agg_c + (size_t)b * NNODES * 12;
    for (int i = t; i < NPB * 12; i += 128) {
        int e = i / 12, cc = i % 12;
        int n = n0 + e;
        float cnt = fmaxf(g_cnt[n], 1.0f);
        outc[n * 12 + cc] = cb[n * 12 + cc] + aggc[n * 12 + cc] / cnt;
    }
}

extern "C" void kernel_launch(void* const* d_in, const int* in_sizes, int n_in,
                              void* d_out, int out_size)
{
    const float* h         = (const float*)d_in[0];
    const float* coord     = (const float*)d_in[1];
    const int*   edge_index= (const int*)  d_in[2];
    const float* edge_attr = (const float*)d_in[3];
    const float* W_e1 = (const float*)d_in[4];
    const float* b_e1 = (const float*)d_in[5];
    const float* W_e2 = (const float*)d_in[6];
    const float* b_e2 = (const float*)d_in[7];
    const float* W_n1 = (const float*)d_in[8];
    const float* b_n1 = (const float*)d_in[9];
    const float* W_n2 = (const float*)d_in[10];
    const float* b_n2 = (const float*)d_in[11];
    const float* W_c1 = (const float*)d_in[12];
    const float* b_c1 = (const float*)d_in[13];
    const float* W_c2 = (const float*)d_in[14];
    float* out = (float*)d_out;

    cudaFuncSetAttribute(edge_kernel,
                         cudaFuncAttributeMaxDynamicSharedMemorySize, SMEM_BYTES);

    prep_kernel<<<(INE * HID + 255) / 256, 256>>>(W_e1, W_e2, W_c1);
    zero_kernel<<<1024, 256>>>();
    count_kernel<<<(NEDGES + 255) / 256, 256>>>(edge_index);
    edge_kernel<<<dim3(NEDGES / MT, NB), 256, SMEM_BYTES>>>(
        h, coord, edge_index, edge_attr, b_e1, b_e2, b_c1, W_c2);
    node_kernel<<<dim3(NNODES / NPB, NB), 128>>>(
        h, coord, W_n1, b_n1, W_n2, b_n2, out);
}

// round 15
// speedup vs baseline: 1.1428x; 1.0048x over previous
#include <cuda_runtime.h>
#include <cstdint>

#define NB 2
#define NNODES 5000
#define NEDGES 160000
#define FIN 128
#define HID 128
#define ED 16
#define INE 288          // 2*FIN + 16 + ED
#define MT 64            // edges per block
#define PAD_H 132        // activation stride (mod 32 == 4 -> conflict-free A frags)
#define KCH 32           // k-chunk per pipeline stage
#define BSTR 136         // B stage row stride (mod 32 == 8 -> conflict-free B frags)
#define BSF (KCH * BSTR) // floats per B stage buffer (4352)
#define NPB 8

// ---------------- scratch (allocation-free) ----------------
__device__ float g_agg_h[NB * NNODES * HID];
__device__ float g_agg_c[NB * NNODES * 12];
__device__ float g_cnt[NNODES];
__device__ __align__(16) float g_We1[INE * HID];
__device__ __align__(16) float g_We2[HID * HID];
__device__ __align__(16) float g_Wc1[HID * HID];

__device__ __forceinline__ float tf32r(float x) {
    uint32_t u;
    asm("cvt.rna.tf32.f32 %0, %1;" : "=r"(u) : "f"(x));
    return __uint_as_float(u);
}

__device__ __forceinline__ void mma_tf32(float c[4], uint32_t a0, uint32_t a1,
                                         uint32_t a2, uint32_t a3,
                                         uint32_t b0, uint32_t b1) {
    asm volatile(
        "mma.sync.aligned.m16n8k8.row.col.f32.tf32.tf32.f32 "
        "{%0,%1,%2,%3},{%4,%5,%6,%7},{%8,%9},{%0,%1,%2,%3};"
        : "+f"(c[0]), "+f"(c[1]), "+f"(c[2]), "+f"(c[3])
        : "r"(a0), "r"(a1), "r"(a2), "r"(a3), "r"(b0), "r"(b1));
}

__device__ __forceinline__ uint32_t smem_u32(const void* p) {
    return (uint32_t)__cvta_generic_to_shared(p);
}
#define CPA16(d, s) asm volatile("cp.async.ca.shared.global [%0], [%1], 16;" :: "r"(d), "l"(s) : "memory")
#define CPC()       asm volatile("cp.async.commit_group;" ::: "memory")
#define CPW(n)      asm volatile("cp.async.wait_group %0;" :: "n"(n) : "memory")

// ---------------- helper kernels ----------------
__global__ void zero_kernel() {
    const int T1 = NB * NNODES * HID;
    const int T2 = T1 + NB * NNODES * 12;
    const int total = T2 + NNODES;
    for (int i = blockIdx.x * blockDim.x + threadIdx.x; i < total;
         i += gridDim.x * blockDim.x) {
        if (i < T1)       g_agg_h[i] = 0.0f;
        else if (i < T2)  g_agg_c[i - T1] = 0.0f;
        else              g_cnt[i - T2] = 0.0f;
    }
}

__global__ void count_kernel(const int* __restrict__ edge_index) {
    int e = blockIdx.x * blockDim.x + threadIdx.x;
    if (e < NEDGES) atomicAdd(&g_cnt[edge_index[e]], 1.0f);
}

__global__ void prep_kernel(const float* __restrict__ W_e1,
                            const float* __restrict__ W_e2,
                            const float* __restrict__ W_c1) {
    int i = blockIdx.x * blockDim.x + threadIdx.x;
    if (i < INE * HID) g_We1[i] = tf32r(W_e1[i]);
    if (i < HID * HID) {
        g_We2[i] = tf32r(W_e2[i]);
        g_Wc1[i] = tf32r(W_c1[i]);
    }
}

__device__ __forceinline__ void init_c(const float* __restrict__ bias,
                                       int n_base, int tig, float c[2][4][4]) {
    #pragma unroll
    for (int nj = 0; nj < 4; nj++) {
        float bv0 = bias[n_base + nj * 8 + 2 * tig];
        float bv1 = bias[n_base + nj * 8 + 2 * tig + 1];
        #pragma unroll
        for (int mi = 0; mi < 2; mi++) {
            c[mi][nj][0] = bv0; c[mi][nj][1] = bv1;
            c[mi][nj][2] = bv0; c[mi][nj][3] = bv1;
        }
    }
}

// ------- block-wide 2-stage (KCH=32) cp.async weight pipeline GEMM -------
// A from smem inS (stride PAD_H); B streamed from Wg (row-major K x HID).
// Accumulates into c. Contains __syncthreads (uniform across block).
template<int NSTAGES>
__device__ __forceinline__ void mma_gemm_st(
    const float* __restrict__ inS, const float* __restrict__ Wg,
    float* __restrict__ bst, int t, int m_base, int n_base, int g, int tig,
    float c[2][4][4])
{
    const int lr = t >> 3;           // stage row 0..31
    const int lc = (t & 7) * 16;     // col 0,16,...,112
    {   // prologue: stage 0
        const float* src = Wg + lr * HID + lc;
        uint32_t d = smem_u32(bst + lr * BSTR + lc);
        CPA16(d, src); CPA16(d + 16, src + 4);
        CPA16(d + 32, src + 8); CPA16(d + 48, src + 12); CPC();
    }
    #pragma unroll
    for (int s = 0; s < NSTAGES; s++) {
        CPW(0);
        __syncthreads();              // stage s visible; all warps done with s-1
        if (s + 1 < NSTAGES) {
            const float* src = Wg + ((s + 1) * KCH + lr) * HID + lc;
            uint32_t d = smem_u32(bst + ((s + 1) & 1) * BSF + lr * BSTR + lc);
            CPA16(d, src); CPA16(d + 16, src + 4);
            CPA16(d + 32, src + 8); CPA16(d + 48, src + 12); CPC();
        }
        const float* pan = bst + (s & 1) * BSF;
        #pragma unroll
        for (int ks = 0; ks < 4; ks++) {
            const int kg = s * KCH + ks * 8;
            uint32_t a[2][4];
            #pragma unroll
            for (int mi = 0; mi < 2; mi++) {
                const float* xr = inS + (m_base + mi * 16 + g) * PAD_H + kg + tig;
                a[mi][0] = __float_as_uint(xr[0]);
                a[mi][1] = __float_as_uint(xr[8 * PAD_H]);
                a[mi][2] = __float_as_uint(xr[4]);
                a[mi][3] = __float_as_uint(xr[8 * PAD_H + 4]);
            }
            uint32_t b0[4], b1[4];
            #pragma unroll
            for (int nj = 0; nj < 4; nj++) {
                b0[nj] = __float_as_uint(pan[(ks * 8 + tig) * BSTR + n_base + nj * 8 + g]);
                b1[nj] = __float_as_uint(pan[(ks * 8 + tig + 4) * BSTR + n_base + nj * 8 + g]);
            }
            #pragma unroll
            for (int nj = 0; nj < 4; nj++)
                #pragma unroll
                for (int mi = 0; mi < 2; mi++)
                    mma_tf32(c[mi][nj], a[mi][0], a[mi][1], a[mi][2], a[mi][3],
                             b0[nj], b1[nj]);
        }
    }
}

// smem float offsets
#define OFF_A   0                          // bufA [MT][PAD_H]: h[row] -> h1 -> h2
#define OFF_B   (MT * PAD_H)               // bufB [MT][PAD_H]: h[col] -> rad/attr -> ef
#define OFF_BS  (OFF_B + MT * PAD_H)       // 2 * BSF weight stages (wsS overlaid)
#define OFF_CDS (OFF_BS + 2 * BSF)
#define OFF_IDX (OFF_CDS + MT * 12)
#define SMEM_FLOATS (OFF_IDX + 2 * MT)
#define SMEM_BYTES  (SMEM_FLOATS * 4)

__global__ __launch_bounds__(256, 2) void edge_kernel(
    const float* __restrict__ h, const float* __restrict__ coord,
    const int* __restrict__ edge_index, const float* __restrict__ edge_attr,
    const float* __restrict__ b_e1, const float* __restrict__ b_e2,
    const float* __restrict__ b_c1, const float* __restrict__ W_c2)
{
    extern __shared__ float sm[];
    float* bufA = sm + OFF_A;
    float* bufB = sm + OFF_B;
    float* bst  = sm + OFF_BS;
    float* wsS  = sm + OFF_BS;    // overlaid: bst dead when wsS is live
    float* cds  = sm + OFF_CDS;
    int* rows_s = (int*)(sm + OFF_IDX);
    int* cols_s = rows_s + MT;

    const int t    = threadIdx.x;
    const int lane = t & 31;
    const int w    = t >> 5;
    const int g    = lane >> 2;
    const int tig  = lane & 3;
    const int m_base = (w >> 2) * 32;   // 2 m-warps
    const int n_base = (w & 3) * 32;    // 4 n-warps

    const int e0 = blockIdx.x * MT;
    const int b  = blockIdx.y;
    const float* hb = h + (size_t)b * NNODES * FIN;
    const float* cb = coord + (size_t)b * NNODES * 12;

    if (t < MT) {
        rows_s[t] = edge_index[e0 + t];
        cols_s[t] = edge_index[NEDGES + e0 + t];
    }
    __syncthreads();

    const int fe = t >> 2, fq = t & 3;   // fill mapping: 64 edges x 4 chunks

    // ---- fill bufA = h[row] via cp.async (HW truncates to tf32 in mma) ----
    {
        const float* src = hb + (size_t)rows_s[fe] * FIN + fq * 32;
        uint32_t d = smem_u32(bufA + fe * PAD_H + fq * 32);
        #pragma unroll
        for (int j = 0; j < 8; j++) CPA16(d + j * 16, src + j * 4);
        CPC();
    }
    // cds (plain loads)
    for (int i = t; i < MT * 12; i += 256) {
        int e = i / 12, cc = i % 12;
        cds[e * 12 + cc] = cb[rows_s[e] * 12 + cc] - cb[cols_s[e] * 12 + cc];
    }

    float c[2][4][4];
    init_c(b_e1, n_base, tig, c);
    // GEMM1 phase A: We1 rows 0..127  (iter-0 CPW+barrier also covers bufA fill)
    mma_gemm_st<4>(bufA, g_We1, bst, t, m_base, n_base, g, tig, c);

    // ---- fill bufB = h[col] (disjoint from bufA/bst reads of lagging warps) ----
    {
        const float* src = hb + (size_t)cols_s[fe] * FIN + fq * 32;
        uint32_t d = smem_u32(bufB + fe * PAD_H + fq * 32);
        #pragma unroll
        for (int j = 0; j < 8; j++) CPA16(d + j * 16, src + j * 4);
        CPC();
    }
    // GEMM1 phase B: We1 rows 128..255
    mma_gemm_st<4>(bufB, g_We1 + 128 * HID, bst, t, m_base, n_base, g, tig, c);

    // ---- fill bufB cols 0..15 = radial, 16..31 = attr (disjoint from lagging
    //      phase-B reads, which touch cols 96..127 at worst) ----
    {
        const float* src = edge_attr + (size_t)(e0 + fe) * ED + fq * 4;
        uint32_t d = smem_u32(bufB + fe * PAD_H + 16 + fq * 4);
        CPA16(d, src); CPC();
    }
    if (t < MT) {
        float cd[12];
        #pragma unroll
        for (int cc = 0; cc < 12; cc++) cd[cc] = cds[t * 12 + cc];
        float prod[16], ss = 0.0f;
        #pragma unroll
        for (int j = 0; j < 4; j++)
            #pragma unroll
            for (int k = 0; k < 4; k++) {
                float p = cd[j*3]*cd[k*3] + cd[j*3+1]*cd[k*3+1] + cd[j*3+2]*cd[k*3+2];
                prod[j * 4 + k] = p;
                ss += p * p;
            }
        float inv = 1.0f / fmaxf(sqrtf(ss), 1e-12f);
        #pragma unroll
        for (int i = 0; i < 16; i++)
            bufB[t * PAD_H + i] = tf32r(prod[i] * inv);
    }
    // GEMM1 phase C: We1 rows 256..287 (1 stage; internal barrier orders fills)
    mma_gemm_st<1>(bufB, g_We1 + 256 * HID, bst, t, m_base, n_base, g, tig, c);

    // h1 = tf32(relu(c)) -> bufA (bufA dead since phase A; writes disjoint from
    // lagging phase-C reads of bufB)
    #pragma unroll
    for (int nj = 0; nj < 4; nj++) {
        int col = n_base + nj * 8 + 2 * tig;
        #pragma unroll
        for (int mi = 0; mi < 2; mi++) {
            int r = m_base + mi * 16 + g;
            bufA[r * PAD_H + col]           = tf32r(fmaxf(c[mi][nj][0], 0.0f));
            bufA[r * PAD_H + col + 1]       = tf32r(fmaxf(c[mi][nj][1], 0.0f));
            bufA[(r + 8) * PAD_H + col]     = tf32r(fmaxf(c[mi][nj][2], 0.0f));
            bufA[(r + 8) * PAD_H + col + 1] = tf32r(fmaxf(c[mi][nj][3], 0.0f));
        }
    }
    __syncthreads();   // REQUIRED: GEMM2 prologue overwrites buf0 still read by phase C

    // GEMM2: h1 @ We2 -> relu -> ef (bufB) ; scatter agg_h from fp32 accums
    init_c(b_e2, n_base, tig, c);
    mma_gemm_st<4>(bufA, g_We2, bst, t, m_base, n_base, g, tig, c);
    {
        float* aggh = g_agg_h + (size_t)b * NNODES * HID;
        #pragma unroll
        for (int nj = 0; nj < 4; nj++) {
            int col = n_base + nj * 8 + 2 * tig;
            #pragma unroll
            for (int mi = 0; mi < 2; mi++) {
                int r = m_base + mi * 16 + g;
                float v0 = fmaxf(c[mi][nj][0], 0.0f), v1 = fmaxf(c[mi][nj][1], 0.0f);
                float v2 = fmaxf(c[mi][nj][2], 0.0f), v3 = fmaxf(c[mi][nj][3], 0.0f);
                bufB[r * PAD_H + col]           = tf32r(v0);
                bufB[r * PAD_H + col + 1]       = tf32r(v1);
                bufB[(r + 8) * PAD_H + col]     = tf32r(v2);
                bufB[(r + 8) * PAD_H + col + 1] = tf32r(v3);
                atomicAdd(&aggh[rows_s[r] * HID + col],         v0);
                atomicAdd(&aggh[rows_s[r] * HID + col + 1],     v1);
                atomicAdd(&aggh[rows_s[r + 8] * HID + col],     v2);
                atomicAdd(&aggh[rows_s[r + 8] * HID + col + 1], v3);
            }
        }
    }
    // (no explicit barrier needed: GEMM3 prologue targets buf0, last read at
    //  GEMM2 stage 2, fenced by stage-3 entry barrier; ef STS ordered by GEMM3's
    //  internal iter-0 barrier)

    // GEMM3: ef @ Wc1 -> relu -> h2 (bufA)
    init_c(b_c1, n_base, tig, c);
    mma_gemm_st<4>(bufB, g_Wc1, bst, t, m_base, n_base, g, tig, c);
    #pragma unroll
    for (int nj = 0; nj < 4; nj++) {
        int col = n_base + nj * 8 + 2 * tig;
        #pragma unroll
        for (int mi = 0; mi < 2; mi++) {
            int r = m_base + mi * 16 + g;
            bufA[r * PAD_H + col]           = fmaxf(c[mi][nj][0], 0.0f);
            bufA[r * PAD_H + col + 1]       = fmaxf(c[mi][nj][1], 0.0f);
            bufA[(r + 8) * PAD_H + col]     = fmaxf(c[mi][nj][2], 0.0f);
            bufA[(r + 8) * PAD_H + col + 1] = fmaxf(c[mi][nj][3], 0.0f);
        }
    }
    __syncthreads();   // REQUIRED: wsS overlays bst; all warps must be past GEMM3

    // GEMM4 (scalar): w = h2 @ W_c2 [HID x 4]; one dot per thread
    {
        int e = t >> 2, cc = t & 3;
        float a = 0.0f;
        #pragma unroll 8
        for (int k = 0; k < HID; k++)
            a = fmaf(bufA[e * PAD_H + k], W_c2[k * 4 + cc], a);
        wsS[e * 4 + cc] = a;
    }
    __syncthreads();

    // coord scatter
    float* aggc = g_agg_c + (size_t)b * NNODES * 12;
    for (int i = t; i < MT * 12; i += 256) {
        int e = i / 12, cc = i % 12;
        atomicAdd(&aggc[rows_s[e] * 12 + cc], cds[e * 12 + cc] * wsS[e * 4 + cc / 3]);
    }
}

// ---------------- node MLP (fp32 scalar) + coord update ----------------
__global__ __launch_bounds__(128) void node_kernel(
    const float* __restrict__ h, const float* __restrict__ coord,
    const float* __restrict__ W_n1, const float* __restrict__ b_n1,
    const float* __restrict__ W_n2, const float* __restrict__ b_n2,
    float* __restrict__ out)
{
    __shared__ float zs[NPB][2 * FIN];
    __shared__ float h1s[NPB][HID];

    const int t  = threadIdx.x;
    const int n0 = blockIdx.x * NPB;
    const int b  = blockIdx.y;
    const float* hb   = h + (size_t)b * NNODES * FIN;
    const float* aggh = g_agg_h + (size_t)b * NNODES * HID;

    #pragma unroll
    for (int e = 0; e < NPB; e++) {
        zs[e][t]       = hb[(n0 + e) * FIN + t];
        zs[e][FIN + t] = aggh[(n0 + e) * HID + t];
    }
    __syncthreads();

    float acc[NPB];
    {
        float bj = b_n1[t];
        #pragma unroll
        for (int e = 0; e < NPB; e++) acc[e] = bj;
        for (int k = 0; k < 2 * FIN; k += 4) {
            float w0 = W_n1[(k + 0) * HID + t];
            float w1 = W_n1[(k + 1) * HID + t];
            float w2 = W_n1[(k + 2) * HID + t];
            float w3 = W_n1[(k + 3) * HID + t];
            #pragma unroll
            for (int e = 0; e < NPB; e++) {
                float4 x4 = *(const float4*)&zs[e][k];
                acc[e] = fmaf(x4.x, w0, fmaf(x4.y, w1, fmaf(x4.z, w2, fmaf(x4.w, w3, acc[e]))));
            }
        }
        #pragma unroll
        for (int e = 0; e < NPB; e++) h1s[e][t] = fmaxf(acc[e], 0.0f);
    }
    __syncthreads();
    {
        float bj = b_n2[t];
        #pragma unroll
        for (int e = 0; e < NPB; e++) acc[e] = bj;
        for (int k = 0; k < HID; k += 4) {
            float w0 = W_n2[(k + 0) * FIN + t];
            float w1 = W_n2[(k + 1) * FIN + t];
            float w2 = W_n2[(k + 2) * FIN + t];
            float w3 = W_n2[(k + 3) * FIN + t];
            #pragma unroll
            for (int e = 0; e < NPB; e++) {
                float4 x4 = *(const float4*)&h1s[e][k];
                acc[e] = fmaf(x4.x, w0, fmaf(x4.y, w1, fmaf(x4.z, w2, fmaf(x4.w, w3, acc[e]))));
            }
        }
    }

    float* outh = out + (size_t)b * NNODES * FIN;
    #pragma unroll
    for (int e = 0; e < NPB; e++)
        outh[(n0 + e) * FIN + t] = zs[e][t] + acc[e];

    float* outc = out + (size_t)NB * NNODES * FIN + (size_t)b * NNODES * 12;
    const float* cb   = coord + (size_t)b * NNODES * 12;
    const float* aggc = g_agg_c + (size_t)b * NNODES * 12;
    for (int i = t; i < NPB * 12; i += 128) {
        int e = i / 12, cc = i % 12;
        int n = n0 + e;
        float cnt = fmaxf(g_cnt[n], 1.0f);
        outc[n * 12 + cc] = cb[n * 12 + cc] + aggc[n * 12 + cc] / cnt;
    }
}

extern "C" void kernel_launch(void* const* d_in, const int* in_sizes, int n_in,
                              void* d_out, int out_size)
{
    const float* h         = (const float*)d_in[0];
    const float* coord     = (const float*)d_in[1];
    const int*   edge_index= (const int*)  d_in[2];
    const float* edge_attr = (const float*)d_in[3];
    const float* W_e1 = (const float*)d_in[4];
    const float* b_e1 = (const float*)d_in[5];
    const float* W_e2 = (const float*)d_in[6];
    const float* b_e2 = (const float*)d_in[7];
    const float* W_n1 = (const float*)d_in[8];
    const float* b_n1 = (const float*)d_in[9];
    const float* W_n2 = (const float*)d_in[10];
    const float* b_n2 = (const float*)d_in[11];
    const float* W_c1 = (const float*)d_in[12];
    const float* b_c1 = (const float*)d_in[13];
    const float* W_c2 = (const float*)d_in[14];
    float* out = (float*)d_out;

    cudaFuncSetAttribute(edge_kernel,
                         cudaFuncAttributeMaxDynamicSharedMemorySize, SMEM_BYTES);

    prep_kernel<<<(INE * HID + 255) / 256, 256>>>(W_e1, W_e2, W_c1);
    zero_kernel<<<1024, 256>>>();
    count_kernel<<<(NEDGES + 255) / 256, 256>>>(edge_index);
    edge_kernel<<<dim3(NEDGES / MT, NB), 256, SMEM_BYTES>>>(
        h, coord, edge_index, edge_attr, b_e1, b_e2, b_c1, W_c2);
    node_kernel<<<dim3(NNODES / NPB, NB), 128>>>(
        h, coord, W_n1, b_n1, W_n2, b_n2, out);
}